// round 2
// baseline (speedup 1.0000x reference)
#include <cuda_runtime.h>
#include <math.h>

#define NN 10000
#define EE 320000
#define DD 256

// ---- scratch (static device globals; no allocation) ----
__device__ float g_esrc[NN * DD];
__device__ float g_edst[NN * DD];
__device__ float g_fsrc[NN * DD];
__device__ float g_agg[NN * DD];
__device__ float g_outdeg[NN];
__device__ float g_indeg[NN];

// ---- zero agg + degrees ----
__global__ void zero_kernel() {
    int i = blockIdx.x * blockDim.x + threadIdx.x;
    if (i < NN * DD) g_agg[i] = 0.f;
    if (i < NN) { g_outdeg[i] = 0.f; g_indeg[i] = 0.f; }
}

// ---- degree accumulation ----
__global__ void degree_kernel(const int* __restrict__ src, const int* __restrict__ dst) {
    int e = blockIdx.x * blockDim.x + threadIdx.x;
    if (e < EE) {
        atomicAdd(&g_outdeg[src[e]], 1.f);
        atomicAdd(&g_indeg[dst[e]], 1.f);
    }
}

// ---- feat_src = node_feats * out_deg^-1/2 ----
__global__ void featsrc_kernel(const float* __restrict__ nodef) {
    int i = blockIdx.x * blockDim.x + threadIdx.x;
    if (i < NN * DD) {
        int r = i / DD;
        g_fsrc[i] = nodef[i] * rsqrtf(fmaxf(g_outdeg[r], 1.f));
    }
}

// ---- tiled GEMM 64x64x16, 256 threads, 4x4 microtile ----
// MODE 0: g_esrc = A@B + bias      (A = node_feats, B = w_src)
// MODE 1: g_edst = A@B + bias      (A = node_feats, B = w_dst)
// MODE 2: edge fused: m = A@B + bias + esrc[src] + edst[dst]; write m to C;
//         scatter feat_src[src]*sigmoid(m) into g_agg[dst]
// MODE 3: final: C = nodef + (g_agg@B)*indeg^-1/2 + bias   (A arg unused; reads g_agg)
template <int MODE>
__global__ void __launch_bounds__(256)
gemm_kernel(const float* __restrict__ A_in, const float* __restrict__ B,
            const float* __restrict__ bias, float* __restrict__ C, int M,
            const int* __restrict__ src, const int* __restrict__ dst,
            const float* __restrict__ nodef)
{
    // Device-side symbol resolution for scratch A (host code must never pass
    // a __device__ symbol — it binds to the host shadow variable).
    const float* A = (MODE == 3) ? (const float*)g_agg : A_in;

    constexpr int BM = 64, BN = 64, BK = 16;
    __shared__ float As[BK][BM + 1];
    __shared__ float Bs[BK][BN];

    const int tid = threadIdx.x;
    const int tx = tid & 15;         // 0..15 (N dim)
    const int ty = tid >> 4;         // 0..15 (M dim)
    const int bm0 = blockIdx.y * BM;
    const int bn0 = blockIdx.x * BN;

    // A-load mapping: 64 rows x 16 k, float4 along k
    const int lrow = tid >> 2;           // 0..63
    const int lk   = (tid & 3) * 4;      // 0,4,8,12
    // B-load mapping: 16 rows x 64 cols, float4 along n
    const int brow = tid >> 4;           // 0..15
    const int bcol = (tid & 15) * 4;

    float acc[4][4];
    #pragma unroll
    for (int i = 0; i < 4; i++)
        #pragma unroll
        for (int j = 0; j < 4; j++) acc[i][j] = 0.f;

    const int ty4 = ty * 4, tx4 = tx * 4;

    for (int k0 = 0; k0 < DD; k0 += BK) {
        float4 av;
        int ar = bm0 + lrow;
        if (ar < M) av = *(const float4*)(A + (size_t)ar * DD + k0 + lk);
        else        av = make_float4(0.f, 0.f, 0.f, 0.f);
        As[lk + 0][lrow] = av.x;
        As[lk + 1][lrow] = av.y;
        As[lk + 2][lrow] = av.z;
        As[lk + 3][lrow] = av.w;

        float4 bv = *(const float4*)(B + (size_t)(k0 + brow) * DD + bn0 + bcol);
        *(float4*)&Bs[brow][bcol] = bv;
        __syncthreads();

        #pragma unroll
        for (int kk = 0; kk < BK; kk++) {
            float a0 = As[kk][ty4 + 0];
            float a1 = As[kk][ty4 + 1];
            float a2 = As[kk][ty4 + 2];
            float a3 = As[kk][ty4 + 3];
            float4 b = *(float4*)&Bs[kk][tx4];
            acc[0][0] += a0 * b.x; acc[0][1] += a0 * b.y; acc[0][2] += a0 * b.z; acc[0][3] += a0 * b.w;
            acc[1][0] += a1 * b.x; acc[1][1] += a1 * b.y; acc[1][2] += a1 * b.z; acc[1][3] += a1 * b.w;
            acc[2][0] += a2 * b.x; acc[2][1] += a2 * b.y; acc[2][2] += a2 * b.z; acc[2][3] += a2 * b.w;
            acc[3][0] += a3 * b.x; acc[3][1] += a3 * b.y; acc[3][2] += a3 * b.z; acc[3][3] += a3 * b.w;
        }
        __syncthreads();
    }

    const float4 bb = *(const float4*)(bias + bn0 + tx4);
    const size_t coloff = (size_t)(bn0 + tx4);

    #pragma unroll
    for (int i = 0; i < 4; i++) {
        int r = bm0 + ty4 + i;
        if (MODE == 0 || MODE == 1) {
            if (r < M) {
                float4 o;
                o.x = acc[i][0] + bb.x; o.y = acc[i][1] + bb.y;
                o.z = acc[i][2] + bb.z; o.w = acc[i][3] + bb.w;
                float* dstp = (MODE == 0 ? g_esrc : g_edst);
                *(float4*)(dstp + (size_t)r * DD + coloff) = o;
            }
        } else if (MODE == 2) {
            // EE % 64 == 0, always in range
            int s = src[r], d = dst[r];
            float4 e1 = *(const float4*)(g_esrc + (size_t)s * DD + coloff);
            float4 e2 = *(const float4*)(g_edst + (size_t)d * DD + coloff);
            float4 f  = *(const float4*)(g_fsrc + (size_t)s * DD + coloff);
            float4 mv;
            mv.x = acc[i][0] + bb.x + e1.x + e2.x;
            mv.y = acc[i][1] + bb.y + e1.y + e2.y;
            mv.z = acc[i][2] + bb.z + e1.z + e2.z;
            mv.w = acc[i][3] + bb.w + e1.w + e2.w;
            *(float4*)(C + (size_t)r * DD + coloff) = mv;
            float s0 = f.x / (1.f + __expf(-mv.x));
            float s1 = f.y / (1.f + __expf(-mv.y));
            float s2 = f.z / (1.f + __expf(-mv.z));
            float s3 = f.w / (1.f + __expf(-mv.w));
            float* ag = g_agg + (size_t)d * DD + coloff;
            atomicAdd(ag + 0, s0);
            atomicAdd(ag + 1, s1);
            atomicAdd(ag + 2, s2);
            atomicAdd(ag + 3, s3);
        } else { // MODE 3
            if (r < M) {
                float nrm = rsqrtf(fmaxf(g_indeg[r], 1.f));
                const float4 nf = *(const float4*)(nodef + (size_t)r * DD + coloff);
                float4 o;
                o.x = nf.x + acc[i][0] * nrm + bb.x;
                o.y = nf.y + acc[i][1] * nrm + bb.y;
                o.z = nf.z + acc[i][2] * nrm + bb.z;
                o.w = nf.w + acc[i][3] * nrm + bb.w;
                *(float4*)(C + (size_t)r * DD + coloff) = o;
            }
        }
    }
}

extern "C" void kernel_launch(void* const* d_in, const int* in_sizes, int n_in,
                              void* d_out, int out_size) {
    const float* nodef  = (const float*)d_in[0];
    const float* edgef  = (const float*)d_in[1];
    const int*   src    = (const int*)d_in[2];
    const int*   dst    = (const int*)d_in[3];
    const float* weight = (const float*)d_in[4];
    const float* bias   = (const float*)d_in[5];
    const float* w_src  = (const float*)d_in[6];
    const float* b_src  = (const float*)d_in[7];
    const float* w_dst  = (const float*)d_in[8];
    const float* b_dst  = (const float*)d_in[9];
    const float* w_edge = (const float*)d_in[10];
    const float* b_edge = (const float*)d_in[11];

    float* rst   = (float*)d_out;                 // [N, D]
    float* m_out = rst + (size_t)NN * DD;         // [E, D]

    // 1. zero scratch
    zero_kernel<<<(NN * DD + 255) / 256, 256>>>();
    // 2. degrees
    degree_kernel<<<(EE + 255) / 256, 256>>>(src, dst);
    // 3. e_src = nodef @ w_src + b_src
    {
        dim3 g(DD / 64, (NN + 63) / 64);
        gemm_kernel<0><<<g, 256>>>(nodef, w_src, b_src, nullptr, NN, nullptr, nullptr, nullptr);
    }
    // 4. e_dst = nodef @ w_dst + b_dst
    {
        dim3 g(DD / 64, (NN + 63) / 64);
        gemm_kernel<1><<<g, 256>>>(nodef, w_dst, b_dst, nullptr, NN, nullptr, nullptr, nullptr);
    }
    // 5. feat_src
    featsrc_kernel<<<(NN * DD + 255) / 256, 256>>>(nodef);
    // 6. edge GEMM + fused gate/sigmoid/scatter
    {
        dim3 g(DD / 64, EE / 64);
        gemm_kernel<2><<<g, 256>>>(edgef, w_edge, b_edge, m_out, EE, src, dst, nullptr);
    }
    // 7. final projection + norm + bias + residual (reads g_agg device-side)
    {
        dim3 g(DD / 64, (NN + 63) / 64);
        gemm_kernel<3><<<g, 256>>>(nullptr, weight, bias, rst, NN, nullptr, nullptr, nodef);
    }
}

// round 4
// speedup vs baseline: 1.3837x; 1.3837x over previous
#include <cuda_runtime.h>
#include <cuda_bf16.h>
#include <cstdint>

#define NN 10000
#define EE 320000
#define DD 256

// ---------------- scratch (static device globals; no allocation) ----------------
__device__ float g_esrc[NN * DD];
__device__ float g_edst[NN * DD];
__device__ float g_fsrc[NN * DD];
__device__ float g_agg[NN * DD];
__device__ float g_outdeg[NN];
__device__ float g_indeg[NN];
// w_edge transposed to [n][k], split into bf16 hi/lo
__device__ unsigned short g_Whi[DD * DD];
__device__ unsigned short g_Wlo[DD * DD];

// ---------------- helpers ----------------
__device__ __forceinline__ uint32_t smem_to_u32(const void* p) {
    uint32_t a;
    asm("{ .reg .u64 t; cvta.to.shared.u64 t, %1; cvt.u32.u64 %0, t; }" : "=r"(a) : "l"(p));
    return a;
}
__device__ __forceinline__ void ldm_x4(uint32_t& r0, uint32_t& r1, uint32_t& r2, uint32_t& r3,
                                       uint32_t addr) {
    asm volatile("ldmatrix.sync.aligned.m8n8.x4.shared.b16 {%0,%1,%2,%3}, [%4];"
                 : "=r"(r0), "=r"(r1), "=r"(r2), "=r"(r3) : "r"(addr));
}
__device__ __forceinline__ void mma16816(float* c, const uint32_t* a, const uint32_t* b) {
    asm volatile(
        "mma.sync.aligned.m16n8k16.row.col.f32.bf16.bf16.f32 "
        "{%0,%1,%2,%3}, {%4,%5,%6,%7}, {%8,%9}, {%0,%1,%2,%3};"
        : "+f"(c[0]), "+f"(c[1]), "+f"(c[2]), "+f"(c[3])
        : "r"(a[0]), "r"(a[1]), "r"(a[2]), "r"(a[3]), "r"(b[0]), "r"(b[1]));
}
// pack two fp32 into bf16x2 hi + residual bf16x2 lo (low 16 bits = first elem)
__device__ __forceinline__ uint32_t split_pair(float a, float b, uint32_t& lo) {
    __nv_bfloat16 ha = __float2bfloat16(a), hb = __float2bfloat16(b);
    __nv_bfloat16 la = __float2bfloat16(a - __bfloat162float(ha));
    __nv_bfloat16 lb = __float2bfloat16(b - __bfloat162float(hb));
    lo = ((uint32_t)__bfloat16_as_ushort(lb) << 16) | (uint32_t)__bfloat16_as_ushort(la);
    return ((uint32_t)__bfloat16_as_ushort(hb) << 16) | (uint32_t)__bfloat16_as_ushort(ha);
}

// ---------------- weight prep: transpose + bf16 split ----------------
__global__ void prep_w_kernel(const float* __restrict__ w_edge) {
    int t = blockIdx.x * blockDim.x + threadIdx.x;  // 8192 threads
    if (t >= 8192) return;
    int n = t & 255;
    int ko = t >> 8;  // 0..31, 8 k each
    #pragma unroll
    for (int j = 0; j < 8; j++) {
        int k = ko * 8 + j;
        float v = w_edge[(size_t)k * DD + n];
        __nv_bfloat16 h = __float2bfloat16(v);
        __nv_bfloat16 l = __float2bfloat16(v - __bfloat162float(h));
        g_Whi[n * DD + k] = __bfloat16_as_ushort(h);
        g_Wlo[n * DD + k] = __bfloat16_as_ushort(l);
    }
}

// ---------------- SMEM layout for edge MMA kernel ----------------
// A/B tiles: 128 rows x 64 bf16, row stride 144B (conflict-free ldmatrix)
static constexpr int RS = 144;
static constexpr int S_AHI = 0;
static constexpr int S_ALO = 128 * RS;          // 18432
static constexpr int S_BHI = 2 * 128 * RS;      // 36864
static constexpr int S_BLO = 3 * 128 * RS;      // 55296
static constexpr int S_TOTAL = 4 * 128 * RS;    // 73728
static constexpr int DS_STRIDE = 136;           // floats; D stage 128 x 136 x 4B = 69632

// ---------------- edge GEMM (mma.sync bf16x3) + fused epilogue ----------------
__global__ void __launch_bounds__(256)
edge_mma_kernel(const float* __restrict__ edgef, const int* __restrict__ src,
                const int* __restrict__ dst, const float* __restrict__ b_edge,
                float* __restrict__ m_out)
{
    extern __shared__ char smem[];
    const uint32_t sb = smem_to_u32(smem);
    const int tid = threadIdx.x;
    const int lane = tid & 31;
    const int wid = tid >> 5;
    const int warp_m = wid & 3;       // 0..3 -> m offset 32*warp_m
    const int warp_n = wid >> 2;      // 0..1 -> n offset 64*warp_n
    const int tile = blockIdx.x;      // edge tile (128 edges)
    const int nBase = blockIdx.y * 128;

    float acc[2][8][4];
    #pragma unroll
    for (int mt = 0; mt < 2; mt++)
        #pragma unroll
        for (int nt = 0; nt < 8; nt++)
            #pragma unroll
            for (int i = 0; i < 4; i++) acc[mt][nt][i] = 0.f;

    // precomputed ldmatrix lane addresses (byte offsets within tile region)
    // A: row = mbase + (lane&15), koff = khalf*16 ; khalf = lane>>4
    const uint32_t a_row = (uint32_t)(lane & 15);
    const uint32_t a_koff = (uint32_t)(lane >> 4) * 16u;
    // B: n = base + (lane&7) + ((lane>>4)<<3), koff = ((lane>>3)&1)*16
    const uint32_t b_n = (uint32_t)((lane & 7) + ((lane >> 4) << 3));
    const uint32_t b_koff = (uint32_t)((lane >> 3) & 1) * 16u;

    for (int kc = 0; kc < 4; kc++) {
        if (kc) __syncthreads();
        // ---- copy B chunk (hi/lo) from prepped global images ----
        {
            const uint4* wh = (const uint4*)g_Whi;
            const uint4* wl = (const uint4*)g_Wlo;
            #pragma unroll
            for (int i = 0; i < 4; i++) {
                int idx = tid + i * 256;          // 0..1023
                int row = idx >> 3, koct = idx & 7;
                // byte offset in global: (nBase+row)*512 + kc*128 + koct*16
                int gi = ((nBase + row) * 512 + kc * 128 + koct * 16) >> 4;
                *(uint4*)(smem + S_BHI + row * RS + koct * 16) = wh[gi];
                *(uint4*)(smem + S_BLO + row * RS + koct * 16) = wl[gi];
            }
        }
        // ---- convert A chunk fp32 -> bf16 hi/lo ----
        #pragma unroll
        for (int i = 0; i < 4; i++) {
            int idx = tid + i * 256;
            int row = idx >> 3, koct = idx & 7;
            const float* p = edgef + (size_t)(tile * 128 + row) * DD + kc * 64 + koct * 8;
            float4 x0 = *(const float4*)p;
            float4 x1 = *(const float4*)(p + 4);
            uint32_t l0, l1, l2, l3;
            uint32_t h0 = split_pair(x0.x, x0.y, l0);
            uint32_t h1 = split_pair(x0.z, x0.w, l1);
            uint32_t h2 = split_pair(x1.x, x1.y, l2);
            uint32_t h3 = split_pair(x1.z, x1.w, l3);
            *(uint4*)(smem + S_AHI + row * RS + koct * 16) = make_uint4(h0, h1, h2, h3);
            *(uint4*)(smem + S_ALO + row * RS + koct * 16) = make_uint4(l0, l1, l2, l3);
        }
        __syncthreads();

        // ---- MMA over 4 k16 steps ----
        #pragma unroll
        for (int ks = 0; ks < 4; ks++) {
            const uint32_t kbyte = (uint32_t)ks * 32u;
            uint32_t ah[2][4], al[2][4];
            #pragma unroll
            for (int mt = 0; mt < 2; mt++) {
                uint32_t roff = (uint32_t)(warp_m * 32 + mt * 16) + a_row;
                uint32_t off = roff * RS + kbyte + a_koff;
                ldm_x4(ah[mt][0], ah[mt][1], ah[mt][2], ah[mt][3], sb + S_AHI + off);
                ldm_x4(al[mt][0], al[mt][1], al[mt][2], al[mt][3], sb + S_ALO + off);
            }
            #pragma unroll
            for (int j = 0; j < 4; j++) {        // pairs of n8 tiles
                uint32_t noff = (uint32_t)(warp_n * 64 + j * 16) + b_n;
                uint32_t off = noff * RS + kbyte + b_koff;
                uint32_t bh[4], bl[4];
                ldm_x4(bh[0], bh[1], bh[2], bh[3], sb + S_BHI + off);
                ldm_x4(bl[0], bl[1], bl[2], bl[3], sb + S_BLO + off);
                #pragma unroll
                for (int mt = 0; mt < 2; mt++) {
                    mma16816(acc[mt][2 * j + 0], ah[mt], bh + 0);
                    mma16816(acc[mt][2 * j + 1], ah[mt], bh + 2);
                    mma16816(acc[mt][2 * j + 0], ah[mt], bl + 0);
                    mma16816(acc[mt][2 * j + 1], ah[mt], bl + 2);
                    mma16816(acc[mt][2 * j + 0], al[mt], bh + 0);
                    mma16816(acc[mt][2 * j + 1], al[mt], bh + 2);
                }
            }
        }
    }
    __syncthreads();

    // ---- stage D to smem (float, stride 136) ----
    {
        float* Ds = (float*)smem;
        const int g = lane >> 2, tg = lane & 3;
        #pragma unroll
        for (int mt = 0; mt < 2; mt++) {
            int r0 = warp_m * 32 + mt * 16 + g;
            #pragma unroll
            for (int nt = 0; nt < 8; nt++) {
                int c = warp_n * 64 + nt * 8 + tg * 2;
                *(float2*)(Ds + r0 * DS_STRIDE + c) = make_float2(acc[mt][nt][0], acc[mt][nt][1]);
                *(float2*)(Ds + (r0 + 8) * DS_STRIDE + c) = make_float2(acc[mt][nt][2], acc[mt][nt][3]);
            }
        }
    }
    __syncthreads();

    // ---- fused epilogue: m = D + bias + esrc[src] + edst[dst]; scatter sigmoid ----
    {
        const float* Ds = (const float*)smem;
        const int row = tid >> 1;
        const int half = (tid & 1) * 64;
        const int e = tile * 128 + row;
        const int s = src[e], d = dst[e];
        const float* pe1 = g_esrc + (size_t)s * DD + nBase;
        const float* pe2 = g_edst + (size_t)d * DD + nBase;
        const float* pf  = g_fsrc + (size_t)s * DD + nBase;
        float* pm = m_out + (size_t)e * DD + nBase;
        float* pa = g_agg + (size_t)d * DD + nBase;
        const float* pb = b_edge + nBase;
        const float* dr = Ds + row * DS_STRIDE;

        #pragma unroll
        for (int j = 0; j < 16; j++) {
            int c = half + j * 4;
            float4 dv = *(const float4*)(dr + c);
            float4 bb = *(const float4*)(pb + c);
            float4 e1 = *(const float4*)(pe1 + c);
            float4 e2 = *(const float4*)(pe2 + c);
            float4 f  = *(const float4*)(pf + c);
            float4 mv;
            mv.x = dv.x + bb.x + e1.x + e2.x;
            mv.y = dv.y + bb.y + e1.y + e2.y;
            mv.z = dv.z + bb.z + e1.z + e2.z;
            mv.w = dv.w + bb.w + e1.w + e2.w;
            *(float4*)(pm + c) = mv;
            float s0 = f.x / (1.f + __expf(-mv.x));
            float s1 = f.y / (1.f + __expf(-mv.y));
            float s2 = f.z / (1.f + __expf(-mv.z));
            float s3 = f.w / (1.f + __expf(-mv.w));
            asm volatile("red.global.add.v4.f32 [%0], {%1,%2,%3,%4};"
                         :: "l"(pa + c), "f"(s0), "f"(s1), "f"(s2), "f"(s3) : "memory");
        }
    }
}

// ---------------- small kernels ----------------
__global__ void zero_kernel() {
    int i = blockIdx.x * blockDim.x + threadIdx.x;
    if (i < NN * DD) g_agg[i] = 0.f;
    if (i < NN) { g_outdeg[i] = 0.f; g_indeg[i] = 0.f; }
}
__global__ void degree_kernel(const int* __restrict__ src, const int* __restrict__ dst) {
    int e = blockIdx.x * blockDim.x + threadIdx.x;
    if (e < EE) {
        atomicAdd(&g_outdeg[src[e]], 1.f);
        atomicAdd(&g_indeg[dst[e]], 1.f);
    }
}
__global__ void featsrc_kernel(const float* __restrict__ nodef) {
    int i = blockIdx.x * blockDim.x + threadIdx.x;
    if (i < NN * DD) {
        int r = i / DD;
        g_fsrc[i] = nodef[i] * rsqrtf(fmaxf(g_outdeg[r], 1.f));
    }
}

// ---- SIMT GEMM 64x64x16 for node-sized matmuls ----
// MODE 0: z=0 -> g_esrc = nodef@w_src+b_src ; z=1 -> g_edst = nodef@w_dst+b_dst
// MODE 3: C = nodef + (g_agg@weight)*indeg^-1/2 + bias
template <int MODE>
__global__ void __launch_bounds__(256)
gemm_kernel(const float* __restrict__ A_in, const float* __restrict__ B0,
            const float* __restrict__ bias0, const float* __restrict__ B1,
            const float* __restrict__ bias1, float* __restrict__ C, int M,
            const float* __restrict__ nodef)
{
    const float* A = (MODE == 3) ? (const float*)g_agg : A_in;
    const float* B = (MODE == 0 && blockIdx.z) ? B1 : B0;
    const float* bias = (MODE == 0 && blockIdx.z) ? bias1 : bias0;

    constexpr int BM = 64, BN = 64, BK = 16;
    __shared__ float As[BK][BM + 1];
    __shared__ float Bs[BK][BN];

    const int tid = threadIdx.x;
    const int tx = tid & 15, ty = tid >> 4;
    const int bm0 = blockIdx.y * BM, bn0 = blockIdx.x * BN;
    const int lrow = tid >> 2, lk = (tid & 3) * 4;
    const int brow = tid >> 4, bcol = (tid & 15) * 4;

    float acc[4][4];
    #pragma unroll
    for (int i = 0; i < 4; i++)
        #pragma unroll
        for (int j = 0; j < 4; j++) acc[i][j] = 0.f;

    const int ty4 = ty * 4, tx4 = tx * 4;
    for (int k0 = 0; k0 < DD; k0 += BK) {
        float4 av;
        int ar = bm0 + lrow;
        if (ar < M) av = *(const float4*)(A + (size_t)ar * DD + k0 + lk);
        else        av = make_float4(0.f, 0.f, 0.f, 0.f);
        As[lk + 0][lrow] = av.x; As[lk + 1][lrow] = av.y;
        As[lk + 2][lrow] = av.z; As[lk + 3][lrow] = av.w;
        *(float4*)&Bs[brow][bcol] = *(const float4*)(B + (size_t)(k0 + brow) * DD + bn0 + bcol);
        __syncthreads();
        #pragma unroll
        for (int kk = 0; kk < BK; kk++) {
            float a0 = As[kk][ty4 + 0], a1 = As[kk][ty4 + 1];
            float a2 = As[kk][ty4 + 2], a3 = As[kk][ty4 + 3];
            float4 b = *(float4*)&Bs[kk][tx4];
            acc[0][0] += a0 * b.x; acc[0][1] += a0 * b.y; acc[0][2] += a0 * b.z; acc[0][3] += a0 * b.w;
            acc[1][0] += a1 * b.x; acc[1][1] += a1 * b.y; acc[1][2] += a1 * b.z; acc[1][3] += a1 * b.w;
            acc[2][0] += a2 * b.x; acc[2][1] += a2 * b.y; acc[2][2] += a2 * b.z; acc[2][3] += a2 * b.w;
            acc[3][0] += a3 * b.x; acc[3][1] += a3 * b.y; acc[3][2] += a3 * b.z; acc[3][3] += a3 * b.w;
        }
        __syncthreads();
    }

    const float4 bb = *(const float4*)(bias + bn0 + tx4);
    const size_t coloff = (size_t)(bn0 + tx4);
    #pragma unroll
    for (int i = 0; i < 4; i++) {
        int r = bm0 + ty4 + i;
        if (r >= M) continue;
        if (MODE == 0) {
            float4 o;
            o.x = acc[i][0] + bb.x; o.y = acc[i][1] + bb.y;
            o.z = acc[i][2] + bb.z; o.w = acc[i][3] + bb.w;
            float* dstp = blockIdx.z ? g_edst : g_esrc;
            *(float4*)(dstp + (size_t)r * DD + coloff) = o;
        } else { // MODE 3
            float nrm = rsqrtf(fmaxf(g_indeg[r], 1.f));
            const float4 nf = *(const float4*)(nodef + (size_t)r * DD + coloff);
            float4 o;
            o.x = nf.x + acc[i][0] * nrm + bb.x;
            o.y = nf.y + acc[i][1] * nrm + bb.y;
            o.z = nf.z + acc[i][2] * nrm + bb.z;
            o.w = nf.w + acc[i][3] * nrm + bb.w;
            *(float4*)(C + (size_t)r * DD + coloff) = o;
        }
    }
}

extern "C" void kernel_launch(void* const* d_in, const int* in_sizes, int n_in,
                              void* d_out, int out_size) {
    const float* nodef  = (const float*)d_in[0];
    const float* edgef  = (const float*)d_in[1];
    const int*   src    = (const int*)d_in[2];
    const int*   dst    = (const int*)d_in[3];
    const float* weight = (const float*)d_in[4];
    const float* bias   = (const float*)d_in[5];
    const float* w_src  = (const float*)d_in[6];
    const float* b_src  = (const float*)d_in[7];
    const float* w_dst  = (const float*)d_in[8];
    const float* b_dst  = (const float*)d_in[9];
    const float* w_edge = (const float*)d_in[10];
    const float* b_edge = (const float*)d_in[11];

    float* rst   = (float*)d_out;             // [N, D]
    float* m_out = rst + (size_t)NN * DD;     // [E, D]

    static bool attr_set = false;
    if (!attr_set) {
        cudaFuncSetAttribute(edge_mma_kernel, cudaFuncAttributeMaxDynamicSharedMemorySize, S_TOTAL);
        attr_set = true;
    }

    prep_w_kernel<<<32, 256>>>(w_edge);
    zero_kernel<<<(NN * DD + 255) / 256, 256>>>();
    degree_kernel<<<(EE + 255) / 256, 256>>>(src, dst);
    {
        dim3 g(DD / 64, (NN + 63) / 64, 2);
        gemm_kernel<0><<<g, 256>>>(nodef, w_src, b_src, w_dst, b_dst, nullptr, NN, nullptr);
    }
    featsrc_kernel<<<(NN * DD + 255) / 256, 256>>>(nodef);
    {
        dim3 g(EE / 128, 2);
        edge_mma_kernel<<<g, 256, S_TOTAL>>>(edgef, src, dst, b_edge, m_out);
    }
    {
        dim3 g(DD / 64, (NN + 63) / 64, 1);
        gemm_kernel<3><<<g, 256>>>(nullptr, weight, bias, nullptr, nullptr, rst, NN, nodef);
    }
}